// round 15
// baseline (speedup 1.0000x reference)
#include <cuda_runtime.h>
#include <cuda_fp16.h>
#include <cstdint>

// Differential attention via mma.sync (HMMA fp16).
//   S = Q K^T (Q pre-scaled by 0.125*log2e), P = exp2(S), O += P V
//   out = (O1/l1 - 0.8*O2/l2) * 0.2, causal.
// 512-thread CTA, 16 warps = (2 streams) x (2 d-halves) x (4 row-groups).
// Each warp: S 16x64 (duplicated across the d-half pair, +33% MMAs) and
// PV 16 rows x 64 dims -> o[8][4]=32 regs. 4 warps/SMSP doubles latency
// hiding vs R13's 2. fp16 Q/K/V pre-converted once; cp.async streaming.

namespace {
constexpr int SEQ = 2048, DIM = 128;
constexpr int BR = 64, BC = 64;
constexpr int QBLKS = SEQ / BR;        // 32
constexpr int SSTR  = 272;             // bytes per 128-fp16 row (+16B pad)
constexpr uint32_t QHo = 0;            // Q [64][128] fp16
constexpr uint32_t KB0 = 17408;        // buffer base
constexpr uint32_t BUFSZ = 34816;      // per-buffer: K + V
__host__ __device__ constexpr uint32_t kh_(int b) { return KB0          + (uint32_t)b * BUFSZ; }
__host__ __device__ constexpr uint32_t vh_(int b) { return KB0 + 17408u + (uint32_t)b * BUFSZ; }
constexpr uint32_t LSo = 87040;        // l sums [2][64] f32
constexpr uint32_t SMEM_TOTAL = 87552;
constexpr int OSTR = 528;              // f32 row stride (bytes) for O exchange
constexpr float EX2C = 0.18033688011112042f;  // log2(e)/8 (folded into Q)
constexpr float LAMBDA = 0.8f, OUT_SCALE = 0.2f;
constexpr int NQ4 = 16 * SEQ * DIM / 4;
constexpr int NK4 = 4  * SEQ * DIM / 4;
}

// fp16 copies (static device memory; no runtime allocation)
__device__ __half g_q16[16 * SEQ * DIM];   // 8 MB (pre-scaled by EX2C)
__device__ __half g_k16[4 * SEQ * DIM];    // 2 MB
__device__ __half g_v16[4 * SEQ * DIM];    // 2 MB

__global__ void cvt_all(const float* __restrict__ Q, const float* __restrict__ K,
                        const float* __restrict__ V) {
    int i = blockIdx.x * blockDim.x + threadIdx.x;
    if (i < NQ4) {
        float4 v = ((const float4*)Q)[i];
        __half2* d = (__half2*)g_q16 + 2 * i;
        d[0] = __floats2half2_rn(v.x * EX2C, v.y * EX2C);
        d[1] = __floats2half2_rn(v.z * EX2C, v.w * EX2C);
    } else if (i < NQ4 + NK4) {
        int j = i - NQ4;
        float4 v = ((const float4*)K)[j];
        __half2* d = (__half2*)g_k16 + 2 * j;
        d[0] = __floats2half2_rn(v.x, v.y);
        d[1] = __floats2half2_rn(v.z, v.w);
    } else if (i < NQ4 + 2 * NK4) {
        int j = i - NQ4 - NK4;
        float4 v = ((const float4*)V)[j];
        __half2* d = (__half2*)g_v16 + 2 * j;
        d[0] = __floats2half2_rn(v.x, v.y);
        d[1] = __floats2half2_rn(v.z, v.w);
    }
}

__device__ __forceinline__ uint32_t smem_u32(const void* p) {
    uint32_t a;
    asm("{ .reg .u64 t; cvta.to.shared.u64 t, %1; cvt.u32.u64 %0, t; }" : "=r"(a) : "l"(p));
    return a;
}
__device__ __forceinline__ uint32_t pkh(float lo, float hi) {
    uint32_t r; asm("cvt.rn.f16x2.f32 %0, %1, %2;" : "=r"(r) : "f"(hi), "f"(lo)); return r;
}
__device__ __forceinline__ float ex2(float x) {
    float y; asm("ex2.approx.f32 %0, %1;" : "=f"(y) : "f"(x)); return y;
}
__device__ __forceinline__ void sts2f(uint32_t a, float x, float y) {
    asm volatile("st.shared.v2.f32 [%0], {%1,%2};" :: "r"(a), "f"(x), "f"(y));
}
__device__ __forceinline__ void cp16(uint32_t s, const void* g) {
    asm volatile("{ .reg .u64 gg; cvta.to.global.u64 gg, %1;\n\t"
                 "cp.async.cg.shared.global [%0], [gg], 16; }" :: "r"(s), "l"(g));
}
__device__ __forceinline__ void cp_commit() { asm volatile("cp.async.commit_group;" ::: "memory"); }
__device__ __forceinline__ void cp_wait0()  { asm volatile("cp.async.wait_group 0;" ::: "memory"); }
__device__ __forceinline__ void ldsm4(uint32_t* r, uint32_t a) {
    asm volatile("ldmatrix.sync.aligned.m8n8.x4.shared.b16 {%0,%1,%2,%3}, [%4];"
        : "=r"(r[0]), "=r"(r[1]), "=r"(r[2]), "=r"(r[3]) : "r"(a));
}
__device__ __forceinline__ void ldsm4t(uint32_t* r, uint32_t a) {
    asm volatile("ldmatrix.sync.aligned.m8n8.x4.trans.shared.b16 {%0,%1,%2,%3}, [%4];"
        : "=r"(r[0]), "=r"(r[1]), "=r"(r[2]), "=r"(r[3]) : "r"(a));
}
__device__ __forceinline__ void mma16816(float* c, const uint32_t* a, const uint32_t* b) {
    asm volatile("mma.sync.aligned.m16n8k16.row.col.f32.f16.f16.f32 "
        "{%0,%1,%2,%3}, {%4,%5,%6,%7}, {%8,%9}, {%0,%1,%2,%3};"
        : "+f"(c[0]), "+f"(c[1]), "+f"(c[2]), "+f"(c[3])
        : "r"(a[0]), "r"(a[1]), "r"(a[2]), "r"(a[3]), "r"(b[0]), "r"(b[1]));
}

// async copy of one 64x128-fp16 tile pair (K,V) into smem (512 threads)
__device__ __forceinline__ void prefetch_kv(uint32_t KHn, uint32_t VHn,
                                            const __half* Kt, const __half* Vt, int tid) {
    #pragma unroll
    for (int it = 0; it < 2; ++it) {
        int idx = tid + it * 512;        // 1024 chunks of 16B per tile
        int r = idx >> 4, cc = idx & 15;
        uint32_t soff = (uint32_t)(r * SSTR + cc * 16);
        cp16(KHn + soff, Kt + r * DIM + cc * 8);
        cp16(VHn + soff, Vt + r * DIM + cc * 8);
    }
}

__global__ __launch_bounds__(512, 1)
void diff_attn_mma(float* __restrict__ O) {
    extern __shared__ char smc[];
    const uint32_t sb = smem_u32(smc);
    const int tid  = threadIdx.x;
    const int lane = tid & 31;
    const int w    = tid >> 5;          // 0..15
    const int strm = w >> 3;            // 0: stream1 (d 0-63), 1: stream2 (d 64-127)
    const int dh   = (w >> 2) & 1;      // output-dim half for PV
    const int mrow = (w & 3) << 4;      // warp's 16 q-rows within the 64-row tile

    const int qb  = QBLKS - 1 - blockIdx.x;   // heavy q-blocks first
    const int h   = blockIdx.y;
    const int kvh = h >> 2;

    const __half* Qg = g_q16 + ((size_t)h * SEQ + (size_t)qb * BR) * DIM;
    const __half* Kg = g_k16 + (size_t)kvh * SEQ * DIM;
    const __half* Vg = g_v16 + (size_t)kvh * SEQ * DIM;

    // ---- async-load Q (16KB) + K/V tile 0 ----
    #pragma unroll
    for (int it = 0; it < 2; ++it) {
        int idx = tid + it * 512;
        int r = idx >> 4, cc = idx & 15;
        cp16(sb + QHo + (uint32_t)(r * SSTR + cc * 16), Qg + r * DIM + cc * 8);
    }
    prefetch_kv(sb + kh_(0), sb + vh_(0), Kg, Vg, tid);
    cp_commit();
    cp_wait0();
    __syncthreads();

    const uint32_t d0  = (uint32_t)(strm * 128);  // Q/K byte offset of stream's dims
    const uint32_t dv0 = (uint32_t)(dh * 128);    // V byte offset of this warp's out dims

    float o[8][4];                       // O accum: 16 rows x 64 dims
    #pragma unroll
    for (int j = 0; j < 8; ++j) { o[j][0]=0.f; o[j][1]=0.f; o[j][2]=0.f; o[j][3]=0.f; }
    float lac0 = 0.f, lac1 = 0.f;

    const int nkb = qb + 1;
    for (int kb = 0; kb < nkb; ++kb) {
        const int cur = kb & 1, nxt = cur ^ 1;
        const uint32_t KHc = sb + kh_(0) + (uint32_t)cur * BUFSZ;
        const uint32_t VHc = KHc + 17408u;
        const bool pf = (kb + 1 < nkb);
        const bool diag = (kb == qb);
        const int row0 = qb * BR + mrow + (lane >> 2);

        // ---- issue async prefetch of next tile (fire & forget) ----
        if (pf) {
            prefetch_kv(sb + kh_(0) + (uint32_t)nxt * BUFSZ,
                        sb + vh_(0) + (uint32_t)nxt * BUFSZ,
                        Kg + (size_t)(kb + 1) * BC * DIM,
                        Vg + (size_t)(kb + 1) * BC * DIM, tid);
            cp_commit();
        }

        float c[8][4];
        #pragma unroll
        for (int j = 0; j < 8; ++j) { c[j][0]=0.f; c[j][1]=0.f; c[j][2]=0.f; c[j][3]=0.f; }

        // ---- S = Q K^T (16 rows x 64 cols; duplicated across the dh pair) ----
        #pragma unroll
        for (int kk = 0; kk < 4; ++kk) {
            uint32_t aaddr = (uint32_t)((mrow + (lane & 15)) * SSTR) + d0
                           + (uint32_t)(kk * 32 + (lane >> 4) * 16);
            uint32_t ah[4];
            ldsm4(ah, sb + QHo + aaddr);
            #pragma unroll
            for (int jj = 0; jj < 4; ++jj) {
                uint32_t baddr = (uint32_t)((16 * jj + (lane & 7) + ((lane >> 4) << 3)) * SSTR)
                               + d0 + (uint32_t)(kk * 32 + ((lane >> 3) & 1) * 16);
                uint32_t bh[4];
                ldsm4(bh, KHc + baddr);
                mma16816(c[2*jj],   ah, bh);
                mma16816(c[2*jj+1], ah, bh + 2);
            }
        }

        // ---- two pipelined halves: softmax (exp2 only; scale pre-folded) + PV ----
        #pragma unroll
        for (int half = 0; half < 2; ++half) {
            #pragma unroll
            for (int jx = 0; jx < 4; ++jx) {
                const int j = half * 4 + jx;
                int colb = kb * BC + 8 * j + 2 * (lane & 3);
                float p0 = ex2(c[j][0]), p1 = ex2(c[j][1]);
                float p2 = ex2(c[j][2]), p3 = ex2(c[j][3]);
                if (diag) {
                    if (colb     > row0)     p0 = 0.f;
                    if (colb + 1 > row0)     p1 = 0.f;
                    if (colb     > row0 + 8) p2 = 0.f;
                    if (colb + 1 > row0 + 8) p3 = 0.f;
                }
                c[j][0] = p0; c[j][1] = p1; c[j][2] = p2; c[j][3] = p3;
                lac0 += p0 + p1;
                lac1 += p2 + p3;
            }

            uint32_t ph[2][4];
            #pragma unroll
            for (int kx = 0; kx < 2; ++kx) {
                const int kk = half * 2 + kx;
                const float* f0 = c[2*kk];
                const float* f1 = c[2*kk+1];
                ph[kx][0] = pkh(f0[0], f0[1]);
                ph[kx][1] = pkh(f0[2], f0[3]);
                ph[kx][2] = pkh(f1[0], f1[1]);
                ph[kx][3] = pkh(f1[2], f1[3]);
            }

            // PV over this warp's 64 output dims (dv0 .. dv0+63)
            #pragma unroll
            for (int kx = 0; kx < 2; ++kx) {
                const int kk = half * 2 + kx;
                #pragma unroll
                for (int jj = 0; jj < 4; ++jj) {
                    uint32_t vaddr = (uint32_t)((16 * kk + (lane & 15)) * SSTR)
                                   + dv0 + (uint32_t)(jj * 32 + (lane >> 4) * 16);
                    uint32_t vh4[4];
                    ldsm4t(vh4, VHc + vaddr);
                    mma16816(o[2*jj],   ph[kx], vh4);
                    mma16816(o[2*jj+1], ph[kx], vh4 + 2);
                }
            }
        }

        if (pf) cp_wait0();
        __syncthreads();   // cur reads done; nxt writes complete+visible
    }

    // ---- epilogue: O frags -> smem (f32), l sums, combine streams ----
    const uint32_t ob = sb + (strm ? kh_(1) : kh_(0));   // reuse K/V regions
    const int r0 = mrow + (lane >> 2);
    #pragma unroll
    for (int j = 0; j < 8; ++j) {
        uint32_t cb = (uint32_t)(dh * 256 + (8 * j + 2 * (lane & 3)) * 4);
        sts2f(ob + (uint32_t)(r0 * OSTR) + cb,       o[j][0], o[j][1]);
        sts2f(ob + (uint32_t)((r0 + 8) * OSTR) + cb, o[j][2], o[j][3]);
    }
    lac0 += __shfl_xor_sync(0xffffffffu, lac0, 1);
    lac0 += __shfl_xor_sync(0xffffffffu, lac0, 2);
    lac1 += __shfl_xor_sync(0xffffffffu, lac1, 1);
    lac1 += __shfl_xor_sync(0xffffffffu, lac1, 2);
    float* ls = (float*)(smc + LSo);
    if (dh == 0 && (lane & 3) == 0) {
        ls[strm * 64 + r0]     = lac0;
        ls[strm * 64 + r0 + 8] = lac1;
    }
    __syncthreads();

    const int er = tid >> 3;            // 0..63
    const int cq = (tid & 7) * 16;
    const float i1 = OUT_SCALE / ls[er];
    const float i2 = OUT_SCALE * LAMBDA / ls[64 + er];
    float* Og = O + ((size_t)h * SEQ + (size_t)qb * BR + er) * DIM + cq;
    #pragma unroll
    for (int u = 0; u < 4; ++u) {
        float4 a = *(const float4*)(smc + kh_(0) + er * OSTR + (cq + 4 * u) * 4);
        float4 b = *(const float4*)(smc + kh_(1) + er * OSTR + (cq + 4 * u) * 4);
        float4 ov;
        ov.x = a.x * i1 - b.x * i2;
        ov.y = a.y * i1 - b.y * i2;
        ov.z = a.z * i1 - b.z * i2;
        ov.w = a.w * i1 - b.w * i2;
        *(float4*)(Og + 4 * u) = ov;
    }
}

extern "C" void kernel_launch(void* const* d_in, const int* in_sizes, int n_in,
                              void* d_out, int out_size) {
    const float* Q = (const float*)d_in[0];
    const float* K = (const float*)d_in[1];
    const float* V = (const float*)d_in[2];
    float* O = (float*)d_out;

    const int ntot = NQ4 + 2 * NK4;
    cvt_all<<<(ntot + 255) / 256, 256>>>(Q, K, V);

    cudaFuncSetAttribute(diff_attn_mma,
                         cudaFuncAttributeMaxDynamicSharedMemorySize, SMEM_TOTAL);
    dim3 grid(QBLKS, 16);   // (32, 16) = 512 CTAs, heavy first
    diff_attn_mma<<<grid, 512, SMEM_TOTAL>>>(O);
}

// round 16
// speedup vs baseline: 1.2029x; 1.2029x over previous
#include <cuda_runtime.h>
#include <cuda_fp16.h>
#include <cstdint>

// Differential attention via mma.sync (HMMA fp16).
//   S = Q K^T (Q pre-scaled by 0.125*log2e), P = exp2(S), O += P V
//   out = (O1/l1 - 0.8*O2/l2) * 0.2, causal.
// 512-thread CTA, 16 warps = (2 streams) x (2 COLUMN-halves) x (4 row-groups).
// Split-K: each warp does S 16x32 (its column half), softmax on 32 cols, and
// PV with partial P (k=32) over all 128 dims -> partial O summed in epilogue.
// Tensor work identical to R13 (no duplication) but 4 warps/SMSP instead of 2.

namespace {
constexpr int SEQ = 2048, DIM = 128;
constexpr int BR = 64, BC = 64;
constexpr int QBLKS = SEQ / BR;        // 32
constexpr int SSTR  = 272;             // bytes per 128-fp16 row (+16B pad)
constexpr uint32_t QHo = 0;            // Q [64][128] fp16
constexpr uint32_t KB0 = 17408;        // buffer base
constexpr uint32_t BUFSZ = 34816;      // per-buffer: K + V
__host__ __device__ constexpr uint32_t kh_(int b) { return KB0          + (uint32_t)b * BUFSZ; }
__host__ __device__ constexpr uint32_t vh_(int b) { return KB0 + 17408u + (uint32_t)b * BUFSZ; }
constexpr int OSTR = 528;              // f32 row stride (bytes) for O exchange
constexpr uint32_t EPSZ = 64 * OSTR;   // 33792 B per partial-O region
__host__ __device__ constexpr uint32_t ep_(int i) { return (uint32_t)i * EPSZ; }
constexpr uint32_t LSo = 4 * EPSZ;             // l sums [4][64] f32 (135168)
constexpr uint32_t SMEM_TOTAL = LSo + 1536;    // 136704 (>= main-loop 87552)
constexpr float EX2C = 0.18033688011112042f;  // log2(e)/8 (folded into Q)
constexpr float LAMBDA = 0.8f, OUT_SCALE = 0.2f;
constexpr int NQ4 = 16 * SEQ * DIM / 4;
constexpr int NK4 = 4  * SEQ * DIM / 4;
}

// fp16 copies (static device memory; no runtime allocation)
__device__ __half g_q16[16 * SEQ * DIM];   // 8 MB (pre-scaled by EX2C)
__device__ __half g_k16[4 * SEQ * DIM];    // 2 MB
__device__ __half g_v16[4 * SEQ * DIM];    // 2 MB

__global__ void cvt_all(const float* __restrict__ Q, const float* __restrict__ K,
                        const float* __restrict__ V) {
    int i = blockIdx.x * blockDim.x + threadIdx.x;
    if (i < NQ4) {
        float4 v = ((const float4*)Q)[i];
        __half2* d = (__half2*)g_q16 + 2 * i;
        d[0] = __floats2half2_rn(v.x * EX2C, v.y * EX2C);
        d[1] = __floats2half2_rn(v.z * EX2C, v.w * EX2C);
    } else if (i < NQ4 + NK4) {
        int j = i - NQ4;
        float4 v = ((const float4*)K)[j];
        __half2* d = (__half2*)g_k16 + 2 * j;
        d[0] = __floats2half2_rn(v.x, v.y);
        d[1] = __floats2half2_rn(v.z, v.w);
    } else if (i < NQ4 + 2 * NK4) {
        int j = i - NQ4 - NK4;
        float4 v = ((const float4*)V)[j];
        __half2* d = (__half2*)g_v16 + 2 * j;
        d[0] = __floats2half2_rn(v.x, v.y);
        d[1] = __floats2half2_rn(v.z, v.w);
    }
}

__device__ __forceinline__ uint32_t smem_u32(const void* p) {
    uint32_t a;
    asm("{ .reg .u64 t; cvta.to.shared.u64 t, %1; cvt.u32.u64 %0, t; }" : "=r"(a) : "l"(p));
    return a;
}
__device__ __forceinline__ uint32_t pkh(float lo, float hi) {
    uint32_t r; asm("cvt.rn.f16x2.f32 %0, %1, %2;" : "=r"(r) : "f"(hi), "f"(lo)); return r;
}
__device__ __forceinline__ float ex2(float x) {
    float y; asm("ex2.approx.f32 %0, %1;" : "=f"(y) : "f"(x)); return y;
}
__device__ __forceinline__ void sts2f(uint32_t a, float x, float y) {
    asm volatile("st.shared.v2.f32 [%0], {%1,%2};" :: "r"(a), "f"(x), "f"(y));
}
__device__ __forceinline__ void cp16(uint32_t s, const void* g) {
    asm volatile("{ .reg .u64 gg; cvta.to.global.u64 gg, %1;\n\t"
                 "cp.async.cg.shared.global [%0], [gg], 16; }" :: "r"(s), "l"(g));
}
__device__ __forceinline__ void cp_commit() { asm volatile("cp.async.commit_group;" ::: "memory"); }
__device__ __forceinline__ void cp_wait0()  { asm volatile("cp.async.wait_group 0;" ::: "memory"); }
__device__ __forceinline__ void ldsm4(uint32_t* r, uint32_t a) {
    asm volatile("ldmatrix.sync.aligned.m8n8.x4.shared.b16 {%0,%1,%2,%3}, [%4];"
        : "=r"(r[0]), "=r"(r[1]), "=r"(r[2]), "=r"(r[3]) : "r"(a));
}
__device__ __forceinline__ void ldsm4t(uint32_t* r, uint32_t a) {
    asm volatile("ldmatrix.sync.aligned.m8n8.x4.trans.shared.b16 {%0,%1,%2,%3}, [%4];"
        : "=r"(r[0]), "=r"(r[1]), "=r"(r[2]), "=r"(r[3]) : "r"(a));
}
__device__ __forceinline__ void mma16816(float* c, const uint32_t* a, const uint32_t* b) {
    asm volatile("mma.sync.aligned.m16n8k16.row.col.f32.f16.f16.f32 "
        "{%0,%1,%2,%3}, {%4,%5,%6,%7}, {%8,%9}, {%0,%1,%2,%3};"
        : "+f"(c[0]), "+f"(c[1]), "+f"(c[2]), "+f"(c[3])
        : "r"(a[0]), "r"(a[1]), "r"(a[2]), "r"(a[3]), "r"(b[0]), "r"(b[1]));
}

// async copy of one 64x128-fp16 tile pair (K,V) into smem (512 threads)
__device__ __forceinline__ void prefetch_kv(uint32_t KHn, uint32_t VHn,
                                            const __half* Kt, const __half* Vt, int tid) {
    #pragma unroll
    for (int it = 0; it < 2; ++it) {
        int idx = tid + it * 512;        // 1024 chunks of 16B per tile
        int r = idx >> 4, cc = idx & 15;
        uint32_t soff = (uint32_t)(r * SSTR + cc * 16);
        cp16(KHn + soff, Kt + r * DIM + cc * 8);
        cp16(VHn + soff, Vt + r * DIM + cc * 8);
    }
}

__global__ __launch_bounds__(512, 1)
void diff_attn_mma(float* __restrict__ O) {
    extern __shared__ char smc[];
    const uint32_t sb = smem_u32(smc);
    const int tid  = threadIdx.x;
    const int lane = tid & 31;
    const int w    = tid >> 5;          // 0..15
    const int strm = w >> 3;            // 0: stream1 (d 0-63), 1: stream2 (d 64-127)
    const int ch   = (w >> 2) & 1;      // S/P column half (kv cols ch*32 .. +31)
    const int mrow = (w & 3) << 4;      // warp's 16 q-rows within the 64-row tile

    const int qb  = QBLKS - 1 - blockIdx.x;   // heavy q-blocks first
    const int h   = blockIdx.y;
    const int kvh = h >> 2;

    const __half* Qg = g_q16 + ((size_t)h * SEQ + (size_t)qb * BR) * DIM;
    const __half* Kg = g_k16 + (size_t)kvh * SEQ * DIM;
    const __half* Vg = g_v16 + (size_t)kvh * SEQ * DIM;

    // ---- async-load Q (16KB) + K/V tile 0 ----
    #pragma unroll
    for (int it = 0; it < 2; ++it) {
        int idx = tid + it * 512;
        int r = idx >> 4, cc = idx & 15;
        cp16(sb + QHo + (uint32_t)(r * SSTR + cc * 16), Qg + r * DIM + cc * 8);
    }
    prefetch_kv(sb + kh_(0), sb + vh_(0), Kg, Vg, tid);
    cp_commit();
    cp_wait0();
    __syncthreads();

    const uint32_t d0 = (uint32_t)(strm * 128);   // Q/K byte offset of stream's dims

    float o[16][4];                      // partial O: 16 rows x 128 dims (k=32 slice)
    #pragma unroll
    for (int j = 0; j < 16; ++j) { o[j][0]=0.f; o[j][1]=0.f; o[j][2]=0.f; o[j][3]=0.f; }
    float lac0 = 0.f, lac1 = 0.f;

    const int nkb = qb + 1;
    for (int kb = 0; kb < nkb; ++kb) {
        const int cur = kb & 1, nxt = cur ^ 1;
        const uint32_t KHc = sb + kh_(0) + (uint32_t)cur * BUFSZ;
        const uint32_t VHc = KHc + 17408u;
        const bool pf = (kb + 1 < nkb);
        const bool diag = (kb == qb);
        const int row0 = qb * BR + mrow + (lane >> 2);

        // ---- issue async prefetch of next tile (fire & forget) ----
        if (pf) {
            prefetch_kv(sb + kh_(0) + (uint32_t)nxt * BUFSZ,
                        sb + vh_(0) + (uint32_t)nxt * BUFSZ,
                        Kg + (size_t)(kb + 1) * BC * DIM,
                        Vg + (size_t)(kb + 1) * BC * DIM, tid);
            cp_commit();
        }

        float c[4][4];                   // S: 16 rows x 32 cols (this warp's half)
        #pragma unroll
        for (int j = 0; j < 4; ++j) { c[j][0]=0.f; c[j][1]=0.f; c[j][2]=0.f; c[j][3]=0.f; }

        // ---- S = Q K^T over this warp's 32 columns ----
        #pragma unroll
        for (int kk = 0; kk < 4; ++kk) {
            uint32_t aaddr = (uint32_t)((mrow + (lane & 15)) * SSTR) + d0
                           + (uint32_t)(kk * 32 + (lane >> 4) * 16);
            uint32_t ah[4];
            ldsm4(ah, sb + QHo + aaddr);
            #pragma unroll
            for (int jl = 0; jl < 2; ++jl) {
                const int jj = ch * 2 + jl;   // global 16-col group
                uint32_t baddr = (uint32_t)((16 * jj + (lane & 7) + ((lane >> 4) << 3)) * SSTR)
                               + d0 + (uint32_t)(kk * 32 + ((lane >> 3) & 1) * 16);
                uint32_t bh[4];
                ldsm4(bh, KHc + baddr);
                mma16816(c[2*jl],   ah, bh);
                mma16816(c[2*jl+1], ah, bh + 2);
            }
        }

        // ---- softmax on 32 cols (exp2 only; scale pre-folded into Q) ----
        #pragma unroll
        for (int j = 0; j < 4; ++j) {
            int colb = kb * BC + ch * 32 + 8 * j + 2 * (lane & 3);
            float p0 = ex2(c[j][0]), p1 = ex2(c[j][1]);
            float p2 = ex2(c[j][2]), p3 = ex2(c[j][3]);
            if (diag) {
                if (colb     > row0)     p0 = 0.f;
                if (colb + 1 > row0)     p1 = 0.f;
                if (colb     > row0 + 8) p2 = 0.f;
                if (colb + 1 > row0 + 8) p3 = 0.f;
            }
            c[j][0] = p0; c[j][1] = p1; c[j][2] = p2; c[j][3] = p3;
            lac0 += p0 + p1;
            lac1 += p2 + p3;
        }

        // ---- P -> fp16 A-frags (k = 32: two kk groups) ----
        uint32_t ph[2][4];
        #pragma unroll
        for (int kx = 0; kx < 2; ++kx) {
            const float* f0 = c[2*kx];
            const float* f1 = c[2*kx+1];
            ph[kx][0] = pkh(f0[0], f0[1]);
            ph[kx][1] = pkh(f0[2], f0[3]);
            ph[kx][2] = pkh(f1[0], f1[1]);
            ph[kx][3] = pkh(f1[2], f1[3]);
        }

        // ---- partial PV: o += P(16x32) V(32x128) ----
        #pragma unroll
        for (int kx = 0; kx < 2; ++kx) {
            const int kkv = ch * 2 + kx;   // global kv 16-row group
            #pragma unroll
            for (int jj = 0; jj < 8; ++jj) {
                uint32_t vaddr = (uint32_t)((16 * kkv + (lane & 15)) * SSTR)
                               + (uint32_t)(jj * 32 + (lane >> 4) * 16);
                uint32_t vh4[4];
                ldsm4t(vh4, VHc + vaddr);
                mma16816(o[2*jj],   ph[kx], vh4);
                mma16816(o[2*jj+1], ph[kx], vh4 + 2);
            }
        }

        if (pf) cp_wait0();
        __syncthreads();   // cur reads done; nxt writes complete+visible
    }

    // ---- epilogue: partial O -> smem region (strm,ch), l partial sums ----
    const uint32_t ob = sb + ep_(strm * 2 + ch);
    const int r0 = mrow + (lane >> 2);
    #pragma unroll
    for (int j = 0; j < 16; ++j) {
        uint32_t cb = (uint32_t)((8 * j + 2 * (lane & 3)) * 4);
        sts2f(ob + (uint32_t)(r0 * OSTR) + cb,       o[j][0], o[j][1]);
        sts2f(ob + (uint32_t)((r0 + 8) * OSTR) + cb, o[j][2], o[j][3]);
    }
    lac0 += __shfl_xor_sync(0xffffffffu, lac0, 1);
    lac0 += __shfl_xor_sync(0xffffffffu, lac0, 2);
    lac1 += __shfl_xor_sync(0xffffffffu, lac1, 1);
    lac1 += __shfl_xor_sync(0xffffffffu, lac1, 2);
    float* ls = (float*)(smc + LSo);
    if ((lane & 3) == 0) {
        ls[(strm * 2 + ch) * 64 + r0]     = lac0;
        ls[(strm * 2 + ch) * 64 + r0 + 8] = lac1;
    }
    __syncthreads();

    // ---- combine: O_s = sum of ch partials; l_s likewise ----
    const int er = tid >> 3;            // 0..63
    const int cq = (tid & 7) * 16;
    const float l1v = ls[er] + ls[64 + er];
    const float l2v = ls[128 + er] + ls[192 + er];
    const float i1 = OUT_SCALE / l1v;
    const float i2 = OUT_SCALE * LAMBDA / l2v;
    float* Og = O + ((size_t)h * SEQ + (size_t)qb * BR + er) * DIM + cq;
    #pragma unroll
    for (int u = 0; u < 4; ++u) {
        uint32_t off = (uint32_t)(er * OSTR + (cq + 4 * u) * 4);
        float4 a0 = *(const float4*)(smc + ep_(0) + off);
        float4 a1 = *(const float4*)(smc + ep_(1) + off);
        float4 b0 = *(const float4*)(smc + ep_(2) + off);
        float4 b1 = *(const float4*)(smc + ep_(3) + off);
        float4 ov;
        ov.x = (a0.x + a1.x) * i1 - (b0.x + b1.x) * i2;
        ov.y = (a0.y + a1.y) * i1 - (b0.y + b1.y) * i2;
        ov.z = (a0.z + a1.z) * i1 - (b0.z + b1.z) * i2;
        ov.w = (a0.w + a1.w) * i1 - (b0.w + b1.w) * i2;
        *(float4*)(Og + 4 * u) = ov;
    }
}

extern "C" void kernel_launch(void* const* d_in, const int* in_sizes, int n_in,
                              void* d_out, int out_size) {
    const float* Q = (const float*)d_in[0];
    const float* K = (const float*)d_in[1];
    const float* V = (const float*)d_in[2];
    float* O = (float*)d_out;

    const int ntot = NQ4 + 2 * NK4;
    cvt_all<<<(ntot + 255) / 256, 256>>>(Q, K, V);

    cudaFuncSetAttribute(diff_attn_mma,
                         cudaFuncAttributeMaxDynamicSharedMemorySize, SMEM_TOTAL);
    dim3 grid(QBLKS, 16);   // (32, 16) = 512 CTAs, heavy first
    diff_attn_mma<<<grid, 512, SMEM_TOTAL>>>(O);
}